// round 9
// baseline (speedup 1.0000x reference)
#include <cuda_runtime.h>
#include <math.h>
#include <stdint.h>

#define B_ 2
#define S_ 2048
#define D_ 1024
#define H_ 16
#define DK_ 64
#define FF_ 4096
#define NEG_ (-1000000000.0f)

// ---------------- scratch buffers ----------------
__device__ float g_n1[(size_t)B_ * S_ * D_];     // tf32 bits
__device__ float g_qkv[(size_t)B_ * S_ * 3 * D_]; // fp32, row stride 3072 (q|k|v)
__device__ float g_o [(size_t)B_ * S_ * D_];     // tf32 bits
__device__ float g_x1[(size_t)B_ * S_ * D_];     // fp32
__device__ float g_n2[(size_t)B_ * S_ * D_];     // tf32 bits
__device__ float g_ff[(size_t)B_ * S_ * FF_];    // tf32 bits
// transposed tf32 weights [N, K]
__device__ uint32_t g_WqkvT[(size_t)(3 * D_) * D_];
__device__ uint32_t g_WoT[(size_t)D_ * D_];
__device__ uint32_t g_W1T[(size_t)FF_ * D_];
__device__ uint32_t g_W2T[(size_t)D_ * FF_];
__device__ float g_bqkv[3 * D_];

__device__ __forceinline__ uint32_t f2tf32(float f) {
    uint32_t r; asm("cvt.rna.tf32.f32 %0, %1;" : "=r"(r) : "f"(f)); return r;
}

__device__ __forceinline__ void mma_tf32(float c[4], const uint32_t a[4], const uint32_t b[2]) {
    asm volatile(
        "mma.sync.aligned.m16n8k8.row.col.f32.tf32.tf32.f32 "
        "{%0,%1,%2,%3}, {%4,%5,%6,%7}, {%8,%9}, {%0,%1,%2,%3};"
        : "+f"(c[0]), "+f"(c[1]), "+f"(c[2]), "+f"(c[3])
        : "r"(a[0]), "r"(a[1]), "r"(a[2]), "r"(a[3]), "r"(b[0]), "r"(b[1]));
}

// ------------- weight transpose + convert: in[Kd,Nd] fp32 -> out[(rowoff+n)*Kd+k] tf32
__global__ __launch_bounds__(256) void cvtT_kernel(const float* __restrict__ in,
                                                   uint32_t* __restrict__ out,
                                                   int Kd, int Nd, int rowoff)
{
    __shared__ float t[32][33];
    const int n0 = blockIdx.x * 32, k0 = blockIdx.y * 32;
    const int tx = threadIdx.x;
#pragma unroll
    for (int y = threadIdx.y; y < 32; y += 8)
        t[y][tx] = in[(size_t)(k0 + y) * Nd + n0 + tx];
    __syncthreads();
#pragma unroll
    for (int y = threadIdx.y; y < 32; y += 8)
        out[(size_t)(rowoff + n0 + y) * Kd + k0 + tx] = f2tf32(t[tx][y]);
}

// ================= tf32 tensor-core GEMM =================
// C[M,N] = act(A[M,K] @ W[K,N] + bias) (+res); A tf32 bits [M,K]; WT tf32 bits [N,K].
#define BM 128
#define BN 128
#define BK 16

__global__ __launch_bounds__(256) void mmagemm_kernel(const uint32_t* __restrict__ A,
                                                      const uint32_t* __restrict__ WT,
                                                      const float* __restrict__ bias,
                                                      const float* __restrict__ res,
                                                      float* __restrict__ C,
                                                      int M, int N, int K, int act, int outtf)
{
    __shared__ alignas(128) char Asm[2 * 8192];
    __shared__ alignas(128) char Bsm[2 * 8192];

    const int tid = threadIdx.x;
    const int wid = tid >> 5, lane = tid & 31;
    const int row0 = blockIdx.y * BM;
    const int col0 = blockIdx.x * BN;

    const int m0w = (wid >> 2) * 64;
    const int n0w = (wid & 3) * 32;
    const int g16b = m0w >> 4;
    const int bg8 = n0w >> 3;

    // A loader: rows (ar, ar+64), cols ac..ac+3
    const int ar = tid >> 2;
    const int ac = (tid & 3) << 2;
    const int lga = ar & 7;
    const int swa = (lga >> 1) & 3;
    const int abase = ((ac >> 3) * 8 + (ar >> 4)) * 512 +
                      ((((ac >> 2) & 1) * 2) + ((ar >> 3) & 1)) * 4;
    int aoff[4];
#pragma unroll
    for (int j = 0; j < 4; j++) aoff[j] = abase + (((lga * 4 + j) ^ swa) << 4);

    // B loader (transposed W): thread -> column n = tid&127, k-half kh = tid>>7
    const int bn = tid & 127;
    const int kh = tid >> 7;            // 0..1 => k offset kh*8, also kb index
    const int bg8l = bn >> 3;
    const int bswz = bg8l & 3;
    int boff[4];
#pragma unroll
    for (int j = 0; j < 4; j++)
        boff[j] = ((kh * 16 + bg8l) << 8) + ((((bn & 7) * 4 + j) ^ bswz) << 3);

    const int aslot = ((lane ^ ((lane >> 3) & 3)) << 4);

    float acc[4][4][4];
#pragma unroll
    for (int mi = 0; mi < 4; mi++)
#pragma unroll
        for (int ni = 0; ni < 4; ni++)
#pragma unroll
            for (int r = 0; r < 4; r++) acc[mi][ni][r] = 0.f;

    const int NC = K / BK;
    const size_t wrow = (size_t)(col0 + bn) * K + kh * 8;

    // prologue
    {
        const uint4 av0 = *reinterpret_cast<const uint4*>(A + (size_t)(row0 + ar) * K + ac);
        const uint4 av1 = *reinterpret_cast<const uint4*>(A + (size_t)(row0 + 64 + ar) * K + ac);
        const uint32_t a0[4] = {av0.x, av0.y, av0.z, av0.w};
        const uint32_t a1[4] = {av1.x, av1.y, av1.z, av1.w};
#pragma unroll
        for (int j = 0; j < 4; j++) {
            *reinterpret_cast<uint32_t*>(Asm + aoff[j]) = a0[j];
            *reinterpret_cast<uint32_t*>(Asm + aoff[j] + 2048) = a1[j];
        }
        const uint4 b0 = *reinterpret_cast<const uint4*>(WT + wrow);
        const uint4 b1 = *reinterpret_cast<const uint4*>(WT + wrow + 4);
        const uint32_t r0[4] = {b0.x, b0.y, b0.z, b0.w};
        const uint32_t r1[4] = {b1.x, b1.y, b1.z, b1.w};
#pragma unroll
        for (int j = 0; j < 4; j++) {
            uint2 u = {r0[j], r1[j]};
            *reinterpret_cast<uint2*>(Bsm + boff[j]) = u;
        }
    }
    __syncthreads();

    for (int c = 0; c < NC; c++) {
        const int buf = c & 1;
        const char* Ab = Asm + buf * 8192;
        const char* Bb = Bsm + buf * 8192;

        uint4 av0, av1, bv0, bv1;
        if (c + 1 < NC) {
            const int k0 = (c + 1) * BK;
            av0 = *reinterpret_cast<const uint4*>(A + (size_t)(row0 + ar) * K + k0 + ac);
            av1 = *reinterpret_cast<const uint4*>(A + (size_t)(row0 + 64 + ar) * K + k0 + ac);
            bv0 = *reinterpret_cast<const uint4*>(WT + wrow + k0);
            bv1 = *reinterpret_cast<const uint4*>(WT + wrow + k0 + 4);
        }

#pragma unroll
        for (int kb = 0; kb < 2; kb++) {
            const char* Abk = Ab + (kb << 12);
            const char* Bbk = Bb + (kb << 12);
            uint4 afr[4];
            uint2 bfr[4];
#pragma unroll
            for (int mi = 0; mi < 4; mi++)
                afr[mi] = *reinterpret_cast<const uint4*>(Abk + ((g16b + mi) << 9) + aslot);
#pragma unroll
            for (int ni = 0; ni < 4; ni++) {
                const int g8 = bg8 + ni;
                bfr[ni] = *reinterpret_cast<const uint2*>(Bbk + (g8 << 8) + ((lane ^ (g8 & 3)) << 3));
            }
#pragma unroll
            for (int mi = 0; mi < 4; mi++)
#pragma unroll
                for (int ni = 0; ni < 4; ni++)
                    mma_tf32(acc[mi][ni],
                             reinterpret_cast<const uint32_t*>(&afr[mi]),
                             reinterpret_cast<const uint32_t*>(&bfr[ni]));
        }

        if (c + 1 < NC) {
            char* An = Asm + (buf ^ 1) * 8192;
            char* Bn = Bsm + (buf ^ 1) * 8192;
            const uint32_t a0[4] = {av0.x, av0.y, av0.z, av0.w};
            const uint32_t a1[4] = {av1.x, av1.y, av1.z, av1.w};
            const uint32_t r0[4] = {bv0.x, bv0.y, bv0.z, bv0.w};
            const uint32_t r1[4] = {bv1.x, bv1.y, bv1.z, bv1.w};
#pragma unroll
            for (int j = 0; j < 4; j++) {
                *reinterpret_cast<uint32_t*>(An + aoff[j]) = a0[j];
                *reinterpret_cast<uint32_t*>(An + aoff[j] + 2048) = a1[j];
                uint2 u = {r0[j], r1[j]};
                *reinterpret_cast<uint2*>(Bn + boff[j]) = u;
            }
            __syncthreads();
        }
    }

    // epilogue
    const int lg = lane >> 2, lt = lane & 3;
#pragma unroll
    for (int mi = 0; mi < 4; mi++) {
#pragma unroll
        for (int half = 0; half < 2; half++) {
            const int r = row0 + m0w + mi * 16 + lg + half * 8;
#pragma unroll
            for (int ni = 0; ni < 4; ni++) {
                const int cc = col0 + n0w + ni * 8 + lt * 2;
                float2 o;
                o.x = acc[mi][ni][half * 2 + 0] + bias[cc];
                o.y = acc[mi][ni][half * 2 + 1] + bias[cc + 1];
                if (act == 1) {
                    o.x = 0.5f * o.x * (1.0f + erff(o.x * 0.70710678118654752f));
                    o.y = 0.5f * o.y * (1.0f + erff(o.y * 0.70710678118654752f));
                }
                if (res) {
                    const float2 rv = *reinterpret_cast<const float2*>(res + (size_t)r * N + cc);
                    o.x += rv.x; o.y += rv.y;
                }
                if (outtf) {
                    o.x = __uint_as_float(f2tf32(o.x));
                    o.y = __uint_as_float(f2tf32(o.y));
                }
                *reinterpret_cast<float2*>(C + (size_t)r * N + cc) = o;
            }
        }
    }
}

// ---------------- LayerNorm (emits tf32 bits) ----------------
__global__ __launch_bounds__(256) void ln_kernel(const float* __restrict__ x,
                                                 const float* __restrict__ g,
                                                 const float* __restrict__ b,
                                                 float* __restrict__ out)
{
    const int row = blockIdx.x;
    const float* xr = x + (size_t)row * D_;
    float* outr = out + (size_t)row * D_;
    const int tid = threadIdx.x;

    float4 v = reinterpret_cast<const float4*>(xr)[tid];
    float s = v.x + v.y + v.z + v.w;
    float ss = v.x * v.x + v.y * v.y + v.z * v.z + v.w * v.w;

    __shared__ float sh_s[8], sh_ss[8];
    for (int off = 16; off; off >>= 1) {
        s  += __shfl_xor_sync(0xffffffffu, s, off);
        ss += __shfl_xor_sync(0xffffffffu, ss, off);
    }
    const int wid = tid >> 5, lane = tid & 31;
    if (lane == 0) { sh_s[wid] = s; sh_ss[wid] = ss; }
    __syncthreads();
    if (wid == 0) {
        s  = (lane < 8) ? sh_s[lane]  : 0.f;
        ss = (lane < 8) ? sh_ss[lane] : 0.f;
        for (int off = 4; off; off >>= 1) {
            s  += __shfl_xor_sync(0xffffffffu, s, off);
            ss += __shfl_xor_sync(0xffffffffu, ss, off);
        }
        if (lane == 0) { sh_s[0] = s; sh_ss[0] = ss; }
    }
    __syncthreads();
    const float mu = sh_s[0] * (1.0f / D_);
    const float var = sh_ss[0] * (1.0f / D_) - mu * mu;
    const float rstd = rsqrtf(var + 1e-5f);

    float4 gv = reinterpret_cast<const float4*>(g)[tid];
    float4 bv = reinterpret_cast<const float4*>(b)[tid];
    uint4 o;
    o.x = f2tf32((v.x - mu) * rstd * gv.x + bv.x);
    o.y = f2tf32((v.y - mu) * rstd * gv.y + bv.y);
    o.z = f2tf32((v.z - mu) * rstd * gv.z + bv.z);
    o.w = f2tf32((v.w - mu) * rstd * gv.w + bv.w);
    reinterpret_cast<uint4*>(outr)[tid] = o;
}

// ================= sparse attention v3 (ldq row stride for q/k/v) ============
#define QB 64
#define KW 192
#define KP 68
#define VP 196
#define ATTN_SMEM ((KW * KP + 64 * VP + 8 * 32) * 4)

__global__ __launch_bounds__(256) void attn3_kernel(const float* __restrict__ Q,
                                                    const float* __restrict__ K,
                                                    const float* __restrict__ V,
                                                    const int* __restrict__ mask,
                                                    float* __restrict__ O,
                                                    int ldq)
{
    extern __shared__ float smattn[];
    float* Ks  = smattn;
    float* Vt  = smattn + KW * KP;
    float* psm = smattn + KW * KP + 64 * VP;

    const int qb0 = blockIdx.x * QB;
    const int h = blockIdx.y;
    const int b = blockIdx.z;
    const int tid = threadIdx.x;
    const int warp = tid >> 5, lane = tid & 31;
    const int base_row = qb0 - 128;

    for (int idx = tid; idx < KW * 64; idx += 256) {
        const int r = idx >> 6, d = idx & 63;
        const int j = base_row + r;
        float kv = 0.f, vv = 0.f;
        if (j >= 0) {
            const size_t g = ((size_t)(b * S_ + j)) * ldq + h * 64 + d;
            kv = K[g]; vv = V[g];
        }
        Ks[r * KP + d] = kv;
        Vt[d * VP + r] = vv;
    }
    __syncthreads();

    float* pb = psm + warp * 32;

#pragma unroll 1
    for (int qi = 0; qi < 8; qi++) {
        const int i = qb0 + warp * 8 + qi;
        const int o_in_blk = warp * 8 + qi;
        const float4* q4 = reinterpret_cast<const float4*>(Q + ((size_t)(b * S_ + i)) * ldq + h * 64);
        float4 rq[16];
#pragma unroll
        for (int d = 0; d < 16; d++) rq[d] = __ldg(q4 + d);
        const int* mrow = mask + (size_t)i * S_;

        float m = -INFINITY, l = 0.f, acc0 = 0.f, acc1 = 0.f;

        // strided keys
        {
            const int j = i - 256 - 128 * lane;
            float s = -INFINITY;
            if (j >= 0) {
                const float4* kr = reinterpret_cast<const float4*>(K + ((size_t)(b * S_ + j)) * ldq + h * 64);
                float dv = 0.f;
#pragma unroll
                for (int d = 0; d < 16; d++) {
                    const float4 kv = __ldg(kr + d);
                    dv = fmaf(rq[d].x, kv.x, dv);
                    dv = fmaf(rq[d].y, kv.y, dv);
                    dv = fmaf(rq[d].z, kv.z, dv);
                    dv = fmaf(rq[d].w, kv.w, dv);
                }
                s = dv * 0.125f;
                if (mrow[j] == 0) s = NEG_;
            }
            float bm = s;
            for (int off = 16; off; off >>= 1)
                bm = fmaxf(bm, __shfl_xor_sync(0xffffffffu, bm, off));
            if (bm > -1e37f) {
                const float nm = fmaxf(m, bm);
                const float sc = __expf(m - nm);
                const float p = __expf(s - nm);
                float bs = p;
                for (int off = 16; off; off >>= 1)
                    bs += __shfl_xor_sync(0xffffffffu, bs, off);
                l = l * sc + bs;
                acc0 *= sc; acc1 *= sc;
                m = nm;
                const int cnt = (i - 256) / 128 + 1;
                for (int l2 = 0; l2 < cnt; l2++) {
                    const float pv = __shfl_sync(0xffffffffu, p, l2);
                    const int j2 = i - 256 - 128 * l2;
                    const float* vr = V + ((size_t)(b * S_ + j2)) * ldq + h * 64;
                    acc0 = fmaf(pv, __ldg(vr + lane), acc0);
                    acc1 = fmaf(pv, __ldg(vr + lane + 32), acc1);
                }
            }
        }

        // local window: 5 aligned 32-key segments
        const int u0 = o_in_blk >> 5;
#pragma unroll 1
        for (int t = 0; t < 5; t++) {
            const int koff = (u0 + t) * 32;
            const int j = base_row + koff + lane;
            float s = -INFINITY;
            if (j >= 0 && j >= i - 128 && j <= i) {
                const float4* kr = reinterpret_cast<const float4*>(Ks + (koff + lane) * KP);
                float dv = 0.f;
#pragma unroll
                for (int d = 0; d < 16; d++) {
                    const float4 kv = kr[d];
                    dv = fmaf(rq[d].x, kv.x, dv);
                    dv = fmaf(rq[d].y, kv.y, dv);
                    dv = fmaf(rq[d].z, kv.z, dv);
                    dv = fmaf(rq[d].w, kv.w, dv);
                }
                s = dv * 0.125f;
                if (mrow[j] == 0) s = NEG_;
            }
            float bm = s;
            for (int off = 16; off; off >>= 1)
                bm = fmaxf(bm, __shfl_xor_sync(0xffffffffu, bm, off));
            if (bm > -1e37f) {
                const float nm = fmaxf(m, bm);
                const float sc = __expf(m - nm);
                const float p = __expf(s - nm);
                float bs = p;
                for (int off = 16; off; off >>= 1)
                    bs += __shfl_xor_sync(0xffffffffu, bs, off);
                l = l * sc + bs;
                acc0 *= sc; acc1 *= sc;
                m = nm;

                __syncwarp();
                pb[lane] = p;
                __syncwarp();
                const float4* pv4 = reinterpret_cast<const float4*>(pb);
                const float4* v0 = reinterpret_cast<const float4*>(Vt + lane * VP + koff);
                const float4* v1 = reinterpret_cast<const float4*>(Vt + (lane + 32) * VP + koff);
#pragma unroll
                for (int kk = 0; kk < 8; kk++) {
                    const float4 pp = pv4[kk];
                    const float4 va = v0[kk];
                    const float4 vb = v1[kk];
                    acc0 = fmaf(pp.x, va.x, acc0);
                    acc0 = fmaf(pp.y, va.y, acc0);
                    acc0 = fmaf(pp.z, va.z, acc0);
                    acc0 = fmaf(pp.w, va.w, acc0);
                    acc1 = fmaf(pp.x, vb.x, acc1);
                    acc1 = fmaf(pp.y, vb.y, acc1);
                    acc1 = fmaf(pp.z, vb.z, acc1);
                    acc1 = fmaf(pp.w, vb.w, acc1);
                }
            }
        }

        const float inv = 1.0f / l;
        float* orow = O + ((size_t)(b * S_ + i)) * D_ + h * 64;
        orow[lane]      = __uint_as_float(f2tf32(acc0 * inv));
        orow[lane + 32] = __uint_as_float(f2tf32(acc1 * inv));
    }
}

// ---------------- host launcher ----------------
extern "C" void kernel_launch(void* const* d_in, const int* in_sizes, int n_in,
                              void* d_out, int out_size)
{
    (void)in_sizes; (void)n_in; (void)out_size;
    const float* x    = (const float*)d_in[0];
    const int*   mask = (const int*)  d_in[1];
    const float* Wq = (const float*)d_in[2];  const float* bq = (const float*)d_in[3];
    const float* Wk = (const float*)d_in[4];  const float* bk = (const float*)d_in[5];
    const float* Wv = (const float*)d_in[6];  const float* bv = (const float*)d_in[7];
    const float* Wo = (const float*)d_in[8];  const float* bo = (const float*)d_in[9];
    const float* W1 = (const float*)d_in[10]; const float* bf1 = (const float*)d_in[11];
    const float* W2 = (const float*)d_in[12]; const float* bf2 = (const float*)d_in[13];
    const float* g1 = (const float*)d_in[14]; const float* bl1 = (const float*)d_in[15];
    const float* g2 = (const float*)d_in[16]; const float* bl2 = (const float*)d_in[17];
    float* out = (float*)d_out;

    float *n1, *qkv, *o, *x1, *n2, *ff, *bqkv;
    uint32_t *WqkvT, *WoT, *W1T, *W2T;
    cudaGetSymbolAddress((void**)&n1, g_n1);
    cudaGetSymbolAddress((void**)&qkv, g_qkv);
    cudaGetSymbolAddress((void**)&o,  g_o);
    cudaGetSymbolAddress((void**)&x1, g_x1);
    cudaGetSymbolAddress((void**)&n2, g_n2);
    cudaGetSymbolAddress((void**)&ff, g_ff);
    cudaGetSymbolAddress((void**)&bqkv, g_bqkv);
    cudaGetSymbolAddress((void**)&WqkvT, g_WqkvT);
    cudaGetSymbolAddress((void**)&WoT, g_WoT);
    cudaGetSymbolAddress((void**)&W1T, g_W1T);
    cudaGetSymbolAddress((void**)&W2T, g_W2T);

    cudaFuncSetAttribute(attn3_kernel, cudaFuncAttributeMaxDynamicSharedMemorySize, ATTN_SMEM);

    const int M = B_ * S_;  // 4096
    dim3 tb(32, 8);

    // 0) weight transpose+convert; bias pack for fused QKV
    cvtT_kernel<<<dim3(D_ / 32, D_ / 32), tb>>>(Wq, WqkvT, D_, D_, 0);
    cvtT_kernel<<<dim3(D_ / 32, D_ / 32), tb>>>(Wk, WqkvT, D_, D_, D_);
    cvtT_kernel<<<dim3(D_ / 32, D_ / 32), tb>>>(Wv, WqkvT, D_, D_, 2 * D_);
    cvtT_kernel<<<dim3(D_ / 32, D_ / 32), tb>>>(Wo, WoT, D_, D_, 0);
    cvtT_kernel<<<dim3(FF_ / 32, D_ / 32), tb>>>(W1, W1T, D_, FF_, 0);
    cvtT_kernel<<<dim3(D_ / 32, FF_ / 32), tb>>>(W2, W2T, FF_, D_, 0);
    cudaMemcpyAsync(bqkv,           bq, D_ * sizeof(float), cudaMemcpyDeviceToDevice);
    cudaMemcpyAsync(bqkv + D_,      bk, D_ * sizeof(float), cudaMemcpyDeviceToDevice);
    cudaMemcpyAsync(bqkv + 2 * D_,  bv, D_ * sizeof(float), cudaMemcpyDeviceToDevice);

    // 1) LN1 -> n1 (tf32)
    ln_kernel<<<M, 256>>>(x, g1, bl1, n1);

    // 2) fused QKV projection -> qkv (fp32, row stride 3072)
    {
        dim3 grid((3 * D_) / BN, M / BM);
        mmagemm_kernel<<<grid, 256>>>((const uint32_t*)n1, WqkvT, bqkv, nullptr, qkv,
                                      M, 3 * D_, D_, 0, 0);
    }

    // 3) sparse attention -> o (tf32)
    {
        dim3 grid(S_ / QB, H_, B_);
        attn3_kernel<<<grid, 256, ATTN_SMEM>>>(qkv, qkv + D_, qkv + 2 * D_, mask, o, 3 * D_);
    }

    // 4) output projection + residual -> x1 (fp32)
    {
        dim3 grid(D_ / BN, M / BM);
        mmagemm_kernel<<<grid, 256>>>((const uint32_t*)o, WoT, bo, x, x1, M, D_, D_, 0, 0);
    }

    // 5) LN2 -> n2 (tf32)
    ln_kernel<<<M, 256>>>(x1, g2, bl2, n2);

    // 6) FFN up + GELU -> ff (tf32)
    {
        dim3 grid(FF_ / BN, M / BM);
        mmagemm_kernel<<<grid, 256>>>((const uint32_t*)n2, W1T, bf1, nullptr, ff, M, FF_, D_, 1, 1);
    }

    // 7) FFN down + residual -> out (fp32)
    {
        dim3 grid(D_ / BN, M / BM);
        mmagemm_kernel<<<grid, 256>>>((const uint32_t*)ff, W2T, bf2, x1, out, M, D_, FF_, 0, 0);
    }
}

// round 10
// speedup vs baseline: 1.2269x; 1.2269x over previous
#include <cuda_runtime.h>
#include <math.h>
#include <stdint.h>

#define B_ 2
#define S_ 2048
#define D_ 1024
#define H_ 16
#define DK_ 64
#define FF_ 4096
#define NEG_ (-1000000000.0f)

// ---------------- scratch buffers ----------------
__device__ float g_n1[(size_t)B_ * S_ * D_];      // tf32 bits
__device__ float g_qkv[(size_t)B_ * S_ * 3 * D_]; // fp32, row stride 3072 (q|k|v)
__device__ float g_o [(size_t)B_ * S_ * D_];      // tf32 bits
__device__ float g_x1[(size_t)B_ * S_ * D_];      // fp32
__device__ float g_n2[(size_t)B_ * S_ * D_];      // tf32 bits
__device__ float g_ff[(size_t)B_ * S_ * FF_];     // tf32 bits
// tf32 weights, [K,N] layout (Wqkv packed column-wise to N=3072)
__device__ uint32_t g_Wqkvc[(size_t)D_ * 3 * D_];
__device__ uint32_t g_Woc[(size_t)D_ * D_];
__device__ uint32_t g_W1c[(size_t)D_ * FF_];
__device__ uint32_t g_W2c[(size_t)FF_ * D_];
__device__ float g_bqkv[3 * D_];

__device__ __forceinline__ uint32_t f2tf32(float f) {
    uint32_t r; asm("cvt.rna.tf32.f32 %0, %1;" : "=r"(r) : "f"(f)); return r;
}

__device__ __forceinline__ void mma_tf32(float c[4], const uint32_t a[4], const uint32_t b[2]) {
    asm volatile(
        "mma.sync.aligned.m16n8k8.row.col.f32.tf32.tf32.f32 "
        "{%0,%1,%2,%3}, {%4,%5,%6,%7}, {%8,%9}, {%0,%1,%2,%3};"
        : "+f"(c[0]), "+f"(c[1]), "+f"(c[2]), "+f"(c[3])
        : "r"(a[0]), "r"(a[1]), "r"(a[2]), "r"(a[3]), "r"(b[0]), "r"(b[1]));
}

// ---------------- weight convert (plain): fp32 [K,N] -> tf32 bits [K,N] -------
__global__ __launch_bounds__(256) void cvtw_kernel(const float* __restrict__ in,
                                                   uint32_t* __restrict__ out)
{
    const int i = (blockIdx.x * 256 + threadIdx.x) * 4;
    const float4 v = *reinterpret_cast<const float4*>(in + i);
    uint4 u;
    u.x = f2tf32(v.x); u.y = f2tf32(v.y); u.z = f2tf32(v.z); u.w = f2tf32(v.w);
    *reinterpret_cast<uint4*>(out + i) = u;
}

// ------- weight convert + column-pack: in[K,1024] -> out[k*3072 + coloff + n] --
__global__ __launch_bounds__(256) void cvtw_pack_kernel(const float* __restrict__ in,
                                                        uint32_t* __restrict__ out,
                                                        int coloff)
{
    const int k = blockIdx.x;                 // one row per block
    const int n = threadIdx.x * 4;
    const float4 v = *reinterpret_cast<const float4*>(in + (size_t)k * D_ + n);
    uint4 u;
    u.x = f2tf32(v.x); u.y = f2tf32(v.y); u.z = f2tf32(v.z); u.w = f2tf32(v.w);
    *reinterpret_cast<uint4*>(out + (size_t)k * (3 * D_) + coloff + n) = u;
}

// ================= tf32 tensor-core GEMM (R8 structure) =======================
#define BM 128
#define BN 128
#define BK 16

__global__ __launch_bounds__(256) void mmagemm_kernel(const uint32_t* __restrict__ A,
                                                      const uint32_t* __restrict__ W,
                                                      const float* __restrict__ bias,
                                                      const float* __restrict__ res,
                                                      float* __restrict__ C,
                                                      int M, int N, int K, int act, int outtf)
{
    __shared__ alignas(128) char Asm[2 * 8192];
    __shared__ alignas(128) char Bsm[2 * 8192];

    const int tid = threadIdx.x;
    const int wid = tid >> 5, lane = tid & 31;
    const int row0 = blockIdx.y * BM;
    const int col0 = blockIdx.x * BN;

    const int m0w = (wid >> 2) * 64;
    const int n0w = (wid & 3) * 32;
    const int g16b = m0w >> 4;
    const int bg8 = n0w >> 3;

    const int ar = tid >> 2;
    const int ac = (tid & 3) << 2;
    const int lga = ar & 7;
    const int swa = (lga >> 1) & 3;
    const int abase = ((ac >> 3) * 8 + (ar >> 4)) * 512 +
                      ((((ac >> 2) & 1) * 2) + ((ar >> 3) & 1)) * 4;
    int aoff[4];
#pragma unroll
    for (int j = 0; j < 4; j++) aoff[j] = abase + (((lga * 4 + j) ^ swa) << 4);

    const int kq = tid >> 6;
    const int nn = tid & 63;
    int boff[2][2];
#pragma unroll
    for (int t = 0; t < 2; t++) {
        const int nv = nn + t * 64;
        const int g8 = nv >> 3;
        const int slot = (((nv & 7) * 4 + kq) ^ (g8 & 3));
#pragma unroll
        for (int kb = 0; kb < 2; kb++)
            boff[t][kb] = ((kb * 16 + g8) << 8) + slot * 8;
    }

    const int aslot = ((lane ^ ((lane >> 3) & 3)) << 4);

    float acc[4][4][4];
#pragma unroll
    for (int mi = 0; mi < 4; mi++)
#pragma unroll
        for (int ni = 0; ni < 4; ni++)
#pragma unroll
            for (int r = 0; r < 4; r++) acc[mi][ni][r] = 0.f;

    const int NC = K / BK;

    // prologue: chunk 0 -> buffer 0
    {
        const uint4 av0 = *reinterpret_cast<const uint4*>(A + (size_t)(row0 + ar) * K + ac);
        const uint4 av1 = *reinterpret_cast<const uint4*>(A + (size_t)(row0 + 64 + ar) * K + ac);
        const uint32_t a0[4] = {av0.x, av0.y, av0.z, av0.w};
        const uint32_t a1[4] = {av1.x, av1.y, av1.z, av1.w};
#pragma unroll
        for (int j = 0; j < 4; j++) {
            *reinterpret_cast<uint32_t*>(Asm + aoff[j]) = a0[j];
            *reinterpret_cast<uint32_t*>(Asm + aoff[j] + 2048) = a1[j];
        }
        uint32_t wreg[2][4];
#pragma unroll
        for (int t = 0; t < 2; t++)
#pragma unroll
            for (int s = 0; s < 4; s++)
                wreg[t][s] = W[(size_t)(kq + s * 4) * N + col0 + nn + t * 64];
#pragma unroll
        for (int t = 0; t < 2; t++)
#pragma unroll
            for (int kb = 0; kb < 2; kb++) {
                uint2 u = {wreg[t][kb * 2 + 0], wreg[t][kb * 2 + 1]};
                *reinterpret_cast<uint2*>(Bsm + boff[t][kb]) = u;
            }
    }
    __syncthreads();

    for (int c = 0; c < NC; c++) {
        const int buf = c & 1;
        const char* Ab = Asm + buf * 8192;
        const char* Bb = Bsm + buf * 8192;

        uint4 av0, av1;
        uint32_t wreg[2][4];
        if (c + 1 < NC) {
            const int k0 = (c + 1) * BK;
            av0 = *reinterpret_cast<const uint4*>(A + (size_t)(row0 + ar) * K + k0 + ac);
            av1 = *reinterpret_cast<const uint4*>(A + (size_t)(row0 + 64 + ar) * K + k0 + ac);
#pragma unroll
            for (int t = 0; t < 2; t++)
#pragma unroll
                for (int s = 0; s < 4; s++)
                    wreg[t][s] = W[(size_t)(k0 + kq + s * 4) * N + col0 + nn + t * 64];
        }

#pragma unroll
        for (int kb = 0; kb < 2; kb++) {
            const char* Abk = Ab + (kb << 12);
            const char* Bbk = Bb + (kb << 12);
            uint4 afr[4];
            uint2 bfr[4];
#pragma unroll
            for (int mi = 0; mi < 4; mi++)
                afr[mi] = *reinterpret_cast<const uint4*>(Abk + ((g16b + mi) << 9) + aslot);
#pragma unroll
            for (int ni = 0; ni < 4; ni++) {
                const int g8 = bg8 + ni;
                bfr[ni] = *reinterpret_cast<const uint2*>(Bbk + (g8 << 8) + ((lane ^ (g8 & 3)) << 3));
            }
#pragma unroll
            for (int mi = 0; mi < 4; mi++)
#pragma unroll
                for (int ni = 0; ni < 4; ni++)
                    mma_tf32(acc[mi][ni],
                             reinterpret_cast<const uint32_t*>(&afr[mi]),
                             reinterpret_cast<const uint32_t*>(&bfr[ni]));
        }

        if (c + 1 < NC) {
            char* An = Asm + (buf ^ 1) * 8192;
            char* Bn = Bsm + (buf ^ 1) * 8192;
            const uint32_t a0[4] = {av0.x, av0.y, av0.z, av0.w};
            const uint32_t a1[4] = {av1.x, av1.y, av1.z, av1.w};
#pragma unroll
            for (int j = 0; j < 4; j++) {
                *reinterpret_cast<uint32_t*>(An + aoff[j]) = a0[j];
                *reinterpret_cast<uint32_t*>(An + aoff[j] + 2048) = a1[j];
            }
#pragma unroll
            for (int t = 0; t < 2; t++)
#pragma unroll
                for (int kb = 0; kb < 2; kb++) {
                    uint2 u = {wreg[t][kb * 2 + 0], wreg[t][kb * 2 + 1]};
                    *reinterpret_cast<uint2*>(Bn + boff[t][kb]) = u;
                }
            __syncthreads();
        }
    }

    // epilogue
    const int lg = lane >> 2, lt = lane & 3;
#pragma unroll
    for (int mi = 0; mi < 4; mi++) {
#pragma unroll
        for (int half = 0; half < 2; half++) {
            const int r = row0 + m0w + mi * 16 + lg + half * 8;
#pragma unroll
            for (int ni = 0; ni < 4; ni++) {
                const int cc = col0 + n0w + ni * 8 + lt * 2;
                float2 o;
                o.x = acc[mi][ni][half * 2 + 0] + bias[cc];
                o.y = acc[mi][ni][half * 2 + 1] + bias[cc + 1];
                if (act == 1) {
                    o.x = 0.5f * o.x * (1.0f + erff(o.x * 0.70710678118654752f));
                    o.y = 0.5f * o.y * (1.0f + erff(o.y * 0.70710678118654752f));
                }
                if (res) {
                    const float2 rv = *reinterpret_cast<const float2*>(res + (size_t)r * N + cc);
                    o.x += rv.x; o.y += rv.y;
                }
                if (outtf) {
                    o.x = __uint_as_float(f2tf32(o.x));
                    o.y = __uint_as_float(f2tf32(o.y));
                }
                *reinterpret_cast<float2*>(C + (size_t)r * N + cc) = o;
            }
        }
    }
}

// ---------------- LayerNorm (emits tf32 bits) ----------------
__global__ __launch_bounds__(256) void ln_kernel(const float* __restrict__ x,
                                                 const float* __restrict__ g,
                                                 const float* __restrict__ b,
                                                 float* __restrict__ out)
{
    const int row = blockIdx.x;
    const float* xr = x + (size_t)row * D_;
    float* outr = out + (size_t)row * D_;
    const int tid = threadIdx.x;

    float4 v = reinterpret_cast<const float4*>(xr)[tid];
    float s = v.x + v.y + v.z + v.w;
    float ss = v.x * v.x + v.y * v.y + v.z * v.z + v.w * v.w;

    __shared__ float sh_s[8], sh_ss[8];
    for (int off = 16; off; off >>= 1) {
        s  += __shfl_xor_sync(0xffffffffu, s, off);
        ss += __shfl_xor_sync(0xffffffffu, ss, off);
    }
    const int wid = tid >> 5, lane = tid & 31;
    if (lane == 0) { sh_s[wid] = s; sh_ss[wid] = ss; }
    __syncthreads();
    if (wid == 0) {
        s  = (lane < 8) ? sh_s[lane]  : 0.f;
        ss = (lane < 8) ? sh_ss[lane] : 0.f;
        for (int off = 4; off; off >>= 1) {
            s  += __shfl_xor_sync(0xffffffffu, s, off);
            ss += __shfl_xor_sync(0xffffffffu, ss, off);
        }
        if (lane == 0) { sh_s[0] = s; sh_ss[0] = ss; }
    }
    __syncthreads();
    const float mu = sh_s[0] * (1.0f / D_);
    const float var = sh_ss[0] * (1.0f / D_) - mu * mu;
    const float rstd = rsqrtf(var + 1e-5f);

    float4 gv = reinterpret_cast<const float4*>(g)[tid];
    float4 bv = reinterpret_cast<const float4*>(b)[tid];
    uint4 o;
    o.x = f2tf32((v.x - mu) * rstd * gv.x + bv.x);
    o.y = f2tf32((v.y - mu) * rstd * gv.y + bv.y);
    o.z = f2tf32((v.z - mu) * rstd * gv.z + bv.z);
    o.w = f2tf32((v.w - mu) * rstd * gv.w + bv.w);
    reinterpret_cast<uint4*>(outr)[tid] = o;
}

// ================= sparse attention v3 (ldq row stride) =================
#define QB 64
#define KW 192
#define KP 68
#define VP 196
#define ATTN_SMEM ((KW * KP + 64 * VP + 8 * 32) * 4)

__global__ __launch_bounds__(256) void attn3_kernel(const float* __restrict__ Q,
                                                    const float* __restrict__ K,
                                                    const float* __restrict__ V,
                                                    const int* __restrict__ mask,
                                                    float* __restrict__ O,
                                                    int ldq)
{
    extern __shared__ float smattn[];
    float* Ks  = smattn;
    float* Vt  = smattn + KW * KP;
    float* psm = smattn + KW * KP + 64 * VP;

    const int qb0 = blockIdx.x * QB;
    const int h = blockIdx.y;
    const int b = blockIdx.z;
    const int tid = threadIdx.x;
    const int warp = tid >> 5, lane = tid & 31;
    const int base_row = qb0 - 128;

    for (int idx = tid; idx < KW * 64; idx += 256) {
        const int r = idx >> 6, d = idx & 63;
        const int j = base_row + r;
        float kv = 0.f, vv = 0.f;
        if (j >= 0) {
            const size_t g = ((size_t)(b * S_ + j)) * ldq + h * 64 + d;
            kv = K[g]; vv = V[g];
        }
        Ks[r * KP + d] = kv;
        Vt[d * VP + r] = vv;
    }
    __syncthreads();

    float* pb = psm + warp * 32;

#pragma unroll 1
    for (int qi = 0; qi < 8; qi++) {
        const int i = qb0 + warp * 8 + qi;
        const int o_in_blk = warp * 8 + qi;
        const float4* q4 = reinterpret_cast<const float4*>(Q + ((size_t)(b * S_ + i)) * ldq + h * 64);
        float4 rq[16];
#pragma unroll
        for (int d = 0; d < 16; d++) rq[d] = __ldg(q4 + d);
        const int* mrow = mask + (size_t)i * S_;

        float m = -INFINITY, l = 0.f, acc0 = 0.f, acc1 = 0.f;

        // strided keys
        {
            const int j = i - 256 - 128 * lane;
            float s = -INFINITY;
            if (j >= 0) {
                const float4* kr = reinterpret_cast<const float4*>(K + ((size_t)(b * S_ + j)) * ldq + h * 64);
                float dv = 0.f;
#pragma unroll
                for (int d = 0; d < 16; d++) {
                    const float4 kv = __ldg(kr + d);
                    dv = fmaf(rq[d].x, kv.x, dv);
                    dv = fmaf(rq[d].y, kv.y, dv);
                    dv = fmaf(rq[d].z, kv.z, dv);
                    dv = fmaf(rq[d].w, kv.w, dv);
                }
                s = dv * 0.125f;
                if (mrow[j] == 0) s = NEG_;
            }
            float bm = s;
            for (int off = 16; off; off >>= 1)
                bm = fmaxf(bm, __shfl_xor_sync(0xffffffffu, bm, off));
            if (bm > -1e37f) {
                const float nm = fmaxf(m, bm);
                const float sc = __expf(m - nm);
                const float p = __expf(s - nm);
                float bs = p;
                for (int off = 16; off; off >>= 1)
                    bs += __shfl_xor_sync(0xffffffffu, bs, off);
                l = l * sc + bs;
                acc0 *= sc; acc1 *= sc;
                m = nm;
                const int cnt = (i - 256) / 128 + 1;
                for (int l2 = 0; l2 < cnt; l2++) {
                    const float pv = __shfl_sync(0xffffffffu, p, l2);
                    const int j2 = i - 256 - 128 * l2;
                    const float* vr = V + ((size_t)(b * S_ + j2)) * ldq + h * 64;
                    acc0 = fmaf(pv, __ldg(vr + lane), acc0);
                    acc1 = fmaf(pv, __ldg(vr + lane + 32), acc1);
                }
            }
        }

        // local window: 5 aligned 32-key segments
        const int u0 = o_in_blk >> 5;
#pragma unroll 1
        for (int t = 0; t < 5; t++) {
            const int koff = (u0 + t) * 32;
            const int j = base_row + koff + lane;
            float s = -INFINITY;
            if (j >= 0 && j >= i - 128 && j <= i) {
                const float4* kr = reinterpret_cast<const float4*>(Ks + (koff + lane) * KP);
                float dv = 0.f;
#pragma unroll
                for (int d = 0; d < 16; d++) {
                    const float4 kv = kr[d];
                    dv = fmaf(rq[d].x, kv.x, dv);
                    dv = fmaf(rq[d].y, kv.y, dv);
                    dv = fmaf(rq[d].z, kv.z, dv);
                    dv = fmaf(rq[d].w, kv.w, dv);
                }
                s = dv * 0.125f;
                if (mrow[j] == 0) s = NEG_;
            }
            float bm = s;
            for (int off = 16; off; off >>= 1)
                bm = fmaxf(bm, __shfl_xor_sync(0xffffffffu, bm, off));
            if (bm > -1e37f) {
                const float nm = fmaxf(m, bm);
                const float sc = __expf(m - nm);
                const float p = __expf(s - nm);
                float bs = p;
                for (int off = 16; off; off >>= 1)
                    bs += __shfl_xor_sync(0xffffffffu, bs, off);
                l = l * sc + bs;
                acc0 *= sc; acc1 *= sc;
                m = nm;

                __syncwarp();
                pb[lane] = p;
                __syncwarp();
                const float4* pv4 = reinterpret_cast<const float4*>(pb);
                const float4* v0 = reinterpret_cast<const float4*>(Vt + lane * VP + koff);
                const float4* v1 = reinterpret_cast<const float4*>(Vt + (lane + 32) * VP + koff);
#pragma unroll
                for (int kk = 0; kk < 8; kk++) {
                    const float4 pp = pv4[kk];
                    const float4 va = v0[kk];
                    const float4 vb = v1[kk];
                    acc0 = fmaf(pp.x, va.x, acc0);
                    acc0 = fmaf(pp.y, va.y, acc0);
                    acc0 = fmaf(pp.z, va.z, acc0);
                    acc0 = fmaf(pp.w, va.w, acc0);
                    acc1 = fmaf(pp.x, vb.x, acc1);
                    acc1 = fmaf(pp.y, vb.y, acc1);
                    acc1 = fmaf(pp.z, vb.z, acc1);
                    acc1 = fmaf(pp.w, vb.w, acc1);
                }
            }
        }

        const float inv = 1.0f / l;
        float* orow = O + ((size_t)(b * S_ + i)) * D_ + h * 64;
        orow[lane]      = __uint_as_float(f2tf32(acc0 * inv));
        orow[lane + 32] = __uint_as_float(f2tf32(acc1 * inv));
    }
}

// ---------------- host launcher ----------------
extern "C" void kernel_launch(void* const* d_in, const int* in_sizes, int n_in,
                              void* d_out, int out_size)
{
    (void)in_sizes; (void)n_in; (void)out_size;
    const float* x    = (const float*)d_in[0];
    const int*   mask = (const int*)  d_in[1];
    const float* Wq = (const float*)d_in[2];  const float* bq = (const float*)d_in[3];
    const float* Wk = (const float*)d_in[4];  const float* bk = (const float*)d_in[5];
    const float* Wv = (const float*)d_in[6];  const float* bv = (const float*)d_in[7];
    const float* Wo = (const float*)d_in[8];  const float* bo = (const float*)d_in[9];
    const float* W1 = (const float*)d_in[10]; const float* bf1 = (const float*)d_in[11];
    const float* W2 = (const float*)d_in[12]; const float* bf2 = (const float*)d_in[13];
    const float* g1 = (const float*)d_in[14]; const float* bl1 = (const float*)d_in[15];
    const float* g2 = (const float*)d_in[16]; const float* bl2 = (const float*)d_in[17];
    float* out = (float*)d_out;

    float *n1, *qkv, *o, *x1, *n2, *ff, *bqkv;
    uint32_t *Wqkvc, *Woc, *W1c, *W2c;
    cudaGetSymbolAddress((void**)&n1, g_n1);
    cudaGetSymbolAddress((void**)&qkv, g_qkv);
    cudaGetSymbolAddress((void**)&o,  g_o);
    cudaGetSymbolAddress((void**)&x1, g_x1);
    cudaGetSymbolAddress((void**)&n2, g_n2);
    cudaGetSymbolAddress((void**)&ff, g_ff);
    cudaGetSymbolAddress((void**)&bqkv, g_bqkv);
    cudaGetSymbolAddress((void**)&Wqkvc, g_Wqkvc);
    cudaGetSymbolAddress((void**)&Woc, g_Woc);
    cudaGetSymbolAddress((void**)&W1c, g_W1c);
    cudaGetSymbolAddress((void**)&W2c, g_W2c);

    cudaFuncSetAttribute(attn3_kernel, cudaFuncAttributeMaxDynamicSharedMemorySize, ATTN_SMEM);

    const int M = B_ * S_;  // 4096

    // 0) weight convert: Wq|Wk|Wv column-packed [1024,3072]; others plain [K,N]
    cvtw_pack_kernel<<<D_, 256>>>(Wq, Wqkvc, 0);
    cvtw_pack_kernel<<<D_, 256>>>(Wk, Wqkvc, D_);
    cvtw_pack_kernel<<<D_, 256>>>(Wv, Wqkvc, 2 * D_);
    cvtw_kernel<<<(D_ * D_) / 1024, 256>>>(Wo, Woc);
    cvtw_kernel<<<(D_ * FF_) / 1024, 256>>>(W1, W1c);
    cvtw_kernel<<<(FF_ * D_) / 1024, 256>>>(W2, W2c);
    cudaMemcpyAsync(bqkv,          bq, D_ * sizeof(float), cudaMemcpyDeviceToDevice);
    cudaMemcpyAsync(bqkv + D_,     bk, D_ * sizeof(float), cudaMemcpyDeviceToDevice);
    cudaMemcpyAsync(bqkv + 2 * D_, bv, D_ * sizeof(float), cudaMemcpyDeviceToDevice);

    // 1) LN1 -> n1 (tf32)
    ln_kernel<<<M, 256>>>(x, g1, bl1, n1);

    // 2) fused QKV projection -> qkv (fp32, row stride 3072)
    {
        dim3 grid((3 * D_) / BN, M / BM);
        mmagemm_kernel<<<grid, 256>>>((const uint32_t*)n1, Wqkvc, bqkv, nullptr, qkv,
                                      M, 3 * D_, D_, 0, 0);
    }

    // 3) sparse attention -> o (tf32)
    {
        dim3 grid(S_ / QB, H_, B_);
        attn3_kernel<<<grid, 256, ATTN_SMEM>>>(qkv, qkv + D_, qkv + 2 * D_, mask, o, 3 * D_);
    }

    // 4) output projection + residual -> x1 (fp32)
    {
        dim3 grid(D_ / BN, M / BM);
        mmagemm_kernel<<<grid, 256>>>((const uint32_t*)o, Woc, bo, x, x1, M, D_, D_, 0, 0);
    }

    // 5) LN2 -> n2 (tf32)
    ln_kernel<<<M, 256>>>(x1, g2, bl2, n2);

    // 6) FFN up + GELU -> ff (tf32)
    {
        dim3 grid(FF_ / BN, M / BM);
        mmagemm_kernel<<<grid, 256>>>((const uint32_t*)n2, W1c, bf1, nullptr, ff, M, FF_, D_, 1, 1);
    }

    // 7) FFN down + residual -> out (fp32)
    {
        dim3 grid(D_ / BN, M / BM);
        mmagemm_kernel<<<grid, 256>>>((const uint32_t*)ff, W2c, bf2, x1, out, M, D_, FF_, 0, 0);
    }
}